// round 1
// baseline (speedup 1.0000x reference)
#include <cuda_runtime.h>
#include <cuda_bf16.h>
#include <cstdint>

// Problem: DepthSeparableConv2d_conv3_4 — dw3x3 + BN1 + ReLU + cut(4.0),
// then pw1x1 + BN2 + ReLU + cut(0.001).
// B=32, C=O=256, H=W=56. All fp32.
//
// Strategy: the dw-stage channel cut (threshold 4.0) zeroes nearly every
// (b,c) plane. Zero planes contribute exactly 0.0f to the pointwise sum,
// so we compute a deterministic per-batch survivor list and run the 1x1
// "GEMM" only over survivors. Handles any survivor count 0..256 correctly.

#define Bn   32
#define Cn   256
#define On   256
#define Hn   56
#define Wn   56
#define HW   3136           // 56*56
#define NPIX_ITER 13        // ceil(3136/256)
#define EPS  1e-5f
#define DW_THR 4.0f
#define PW_THR 0.001f

// Scratch: y planes (only surviving planes are written each launch; pw stage
// only reads channels flagged in THIS launch, so stale data is never read).
__device__ float g_y[(size_t)Bn * Cn * HW];     // ~102.8 MB
__device__ int   g_flags[Bn * Cn];              // 0/1 per (b,c), fully rewritten each launch

// ---------------------------------------------------------------------------
// Kernel A: depthwise 3x3 (cross-correlation, pad 1) + bias + BN1 + ReLU,
// per-plane max, flag + conditional plane write. One block per (b,c).
// ---------------------------------------------------------------------------
__global__ __launch_bounds__(256)
void dw_kernel(const float* __restrict__ x,
               const float* __restrict__ dw_w,   // [C,1,3,3]
               const float* __restrict__ dw_b,   // [C]
               const float* __restrict__ g1, const float* __restrict__ b1,
               const float* __restrict__ m1, const float* __restrict__ v1)
{
    const int plane = blockIdx.x;          // b*Cn + c
    const int c     = plane & (Cn - 1);
    const int tid   = threadIdx.x;

    __shared__ float tile[58 * 58];

    const float* __restrict__ xp = x + (size_t)plane * HW;

    // Load 58x58 haloed tile (zero padding outside the 56x56 plane).
    for (int i = tid; i < 58 * 58; i += 256) {
        int r  = i / 58;
        int cc = i - r * 58;
        int gr = r - 1, gc = cc - 1;
        float v = 0.0f;
        if ((unsigned)gr < (unsigned)Hn && (unsigned)gc < (unsigned)Wn)
            v = xp[gr * Wn + gc];
        tile[i] = v;
    }

    // Per-channel constants.
    float w[9];
#pragma unroll
    for (int k = 0; k < 9; k++) w[k] = dw_w[c * 9 + k];
    const float bias = dw_b[c];
    const float inv  = g1[c] * rsqrtf(v1[c] + EPS);
    const float add  = b1[c] - m1[c] * inv;

    __syncthreads();

    // Compute 13 pixels/thread, keep results in registers, track max.
    float vals[NPIX_ITER];
    float mx = 0.0f;
#pragma unroll
    for (int i = 0; i < NPIX_ITER; i++) {
        int p = tid + i * 256;
        float r = 0.0f;
        if (p < HW) {
            int h = p / Wn;
            int ww = p - h * Wn;
            const float* t = &tile[h * 58 + ww];
            float acc = bias;
            acc = fmaf(w[0], t[0],   acc);
            acc = fmaf(w[1], t[1],   acc);
            acc = fmaf(w[2], t[2],   acc);
            acc = fmaf(w[3], t[58],  acc);
            acc = fmaf(w[4], t[59],  acc);
            acc = fmaf(w[5], t[60],  acc);
            acc = fmaf(w[6], t[116], acc);
            acc = fmaf(w[7], t[117], acc);
            acc = fmaf(w[8], t[118], acc);
            r = fmaxf(fmaf(acc, inv, add), 0.0f);   // BN1 + ReLU
            mx = fmaxf(mx, r);
        }
        vals[i] = r;
    }

    // Block max reduction (values are >= 0).
    __shared__ float smax[8];
    __shared__ int   s_keep;
    const int lane = tid & 31, warp = tid >> 5;
#pragma unroll
    for (int off = 16; off; off >>= 1)
        mx = fmaxf(mx, __shfl_xor_sync(0xffffffffu, mx, off));
    if (lane == 0) smax[warp] = mx;
    __syncthreads();
    if (tid == 0) {
        float m = smax[0];
#pragma unroll
        for (int i = 1; i < 8; i++) m = fmaxf(m, smax[i]);
        int keep = (m >= DW_THR) ? 1 : 0;   // reference zeroes when max_abs < thr
        s_keep = keep;
        g_flags[plane] = keep;
    }
    __syncthreads();

    if (s_keep) {
        float* __restrict__ yp = g_y + (size_t)plane * HW;
#pragma unroll
        for (int i = 0; i < NPIX_ITER; i++) {
            int p = tid + i * 256;
            if (p < HW) yp[p] = vals[i];
        }
    }
}

// ---------------------------------------------------------------------------
// Kernel B: pointwise 1x1 over surviving channels + bias + BN2 + ReLU,
// per-plane max cut. One block per (b,o).
// ---------------------------------------------------------------------------
__global__ __launch_bounds__(256)
void pw_kernel(const float* __restrict__ pw_w,   // [O,C]
               const float* __restrict__ pw_b,   // [O]
               const float* __restrict__ g2, const float* __restrict__ b2,
               const float* __restrict__ m2, const float* __restrict__ v2,
               float* __restrict__ z)
{
    const int bo  = blockIdx.x;        // b*On + o
    const int b   = bo >> 8;
    const int o   = bo & (On - 1);
    const int tid = threadIdx.x;
    const int lane = tid & 31, warp = tid >> 5;

    __shared__ int   soff[Cn];         // surviving-channel element offsets (c*HW)
    __shared__ float sw[Cn];           // matching pw weights
    __shared__ int   warpcnt[8];
    __shared__ int   s_n;
    __shared__ int   s_keep;

    // Deterministic ballot-compaction of this batch's survivors (ascending c).
    const int c = tid;
    const int f = g_flags[b * Cn + c];
    unsigned ball = __ballot_sync(0xffffffffu, f);
    if (lane == 0) warpcnt[warp] = __popc(ball);
    __syncthreads();
    int prefix = 0;
#pragma unroll
    for (int i = 0; i < 8; i++) prefix += (i < warp) ? warpcnt[i] : 0;
    if (f) {
        int pos = prefix + __popc(ball & ((1u << lane) - 1u));
        soff[pos] = c * HW;
        sw[pos]   = pw_w[o * Cn + c];
    }
    if (tid == 0) {
        int n = 0;
#pragma unroll
        for (int i = 0; i < 8; i++) n += warpcnt[i];
        s_n = n;
    }
    __syncthreads();
    const int n = s_n;

    const float bias = pw_b[o];
    const float inv  = g2[o] * rsqrtf(v2[o] + EPS);
    const float add  = b2[o] - m2[o] * inv;

    const float* __restrict__ yb = g_y + (size_t)b * Cn * HW;

    float acc[NPIX_ITER];
#pragma unroll
    for (int i = 0; i < NPIX_ITER; i++) acc[i] = bias;

    // Survivor-major loop: 13 independent coalesced loads per survivor (MLP).
    for (int j = 0; j < n; j++) {
        const float wj = sw[j];
        const float* __restrict__ yp = yb + soff[j];
#pragma unroll
        for (int i = 0; i < NPIX_ITER; i++) {
            int p = tid + i * 256;
            if (p < HW) acc[i] = fmaf(wj, yp[p], acc[i]);
        }
    }

    // BN2 + ReLU, per-thread max.
    float mx = 0.0f;
#pragma unroll
    for (int i = 0; i < NPIX_ITER; i++) {
        int p = tid + i * 256;
        float r = fmaxf(fmaf(acc[i], inv, add), 0.0f);
        acc[i] = r;
        if (p < HW) mx = fmaxf(mx, r);
    }

    __shared__ float smax[8];
#pragma unroll
    for (int off = 16; off; off >>= 1)
        mx = fmaxf(mx, __shfl_xor_sync(0xffffffffu, mx, off));
    if (lane == 0) smax[warp] = mx;
    __syncthreads();
    if (tid == 0) {
        float m = smax[0];
#pragma unroll
        for (int i = 1; i < 8; i++) m = fmaxf(m, smax[i]);
        s_keep = (m >= PW_THR) ? 1 : 0;
    }
    __syncthreads();
    const float scale = s_keep ? 1.0f : 0.0f;   // cut -> exact zeros

    float* __restrict__ zp = z + (size_t)bo * HW;
#pragma unroll
    for (int i = 0; i < NPIX_ITER; i++) {
        int p = tid + i * 256;
        if (p < HW) zp[p] = acc[i] * scale;
    }
}

// ---------------------------------------------------------------------------
// Launch. Inputs in setup_inputs() order:
// 0:x 1:dw_w 2:dw_b 3:pw_w 4:pw_b
// 5:bn1_gamma 6:bn1_beta 7:bn1_mean 8:bn1_var
// 9:bn2_gamma 10:bn2_beta 11:bn2_mean 12:bn2_var
// ---------------------------------------------------------------------------
extern "C" void kernel_launch(void* const* d_in, const int* in_sizes, int n_in,
                              void* d_out, int out_size)
{
    const float* x    = (const float*)d_in[0];
    const float* dw_w = (const float*)d_in[1];
    const float* dw_b = (const float*)d_in[2];
    const float* pw_w = (const float*)d_in[3];
    const float* pw_b = (const float*)d_in[4];
    const float* g1   = (const float*)d_in[5];
    const float* b1   = (const float*)d_in[6];
    const float* m1   = (const float*)d_in[7];
    const float* v1   = (const float*)d_in[8];
    const float* g2   = (const float*)d_in[9];
    const float* b2   = (const float*)d_in[10];
    const float* m2   = (const float*)d_in[11];
    const float* v2   = (const float*)d_in[12];
    float* z = (float*)d_out;

    dw_kernel<<<Bn * Cn, 256>>>(x, dw_w, dw_b, g1, b1, m1, v1);
    pw_kernel<<<Bn * On, 256>>>(pw_w, pw_b, g2, b2, m2, v2, z);
}

// round 2
// speedup vs baseline: 1.6616x; 1.6616x over previous
#include <cuda_runtime.h>
#include <cuda_bf16.h>
#include <cstdint>

// DepthSeparableConv2d_conv3_4: dw3x3+BN1+ReLU+cut(4.0) -> pw1x1+BN2+ReLU+cut(0.001)
// B=32, C=O=256, H=W=56. Survivor-sparse pointwise GEMM.

#define Bn   32
#define Cn   256
#define On   256
#define Hn   56
#define Wn   56
#define HW   3136           // 56*56
#define HW4  784            // HW/4
#define EPS  1e-5f
#define DW_THR 4.0f
#define PW_THR 0.001f
#define TO   8              // output channels per pw block

// Scratch: y planes (only surviving planes written per launch) + survivor flags.
__device__ float g_y[(size_t)Bn * Cn * HW];
__device__ int   g_flags[Bn * Cn];

// ---------------------------------------------------------------------------
// Kernel A: depthwise 3x3 + bias + BN1 + ReLU + plane max + conditional write.
// One block per (b,c) plane; 224 threads. Thread = (column w, 14-row strip).
// Rolling 3x3 register window: 3 LDS per output row instead of 9.
// ---------------------------------------------------------------------------
__global__ __launch_bounds__(224)
void dw_kernel(const float* __restrict__ x,
               const float* __restrict__ dw_w,   // [C,1,3,3]
               const float* __restrict__ dw_b,   // [C]
               const float* __restrict__ g1, const float* __restrict__ b1,
               const float* __restrict__ m1, const float* __restrict__ v1)
{
    const int plane = blockIdx.x;          // b*Cn + c
    const int c     = plane & (Cn - 1);
    const int tid   = threadIdx.x;

    __shared__ float tile[HW];             // 56x56, no halo (guards in compute)

    // Cooperative float4 tile load (plane is 16B-aligned, contiguous).
    {
        const float4* __restrict__ xp4 = (const float4*)(x + (size_t)plane * HW);
        float4* __restrict__ t4 = (float4*)tile;
#pragma unroll
        for (int it = 0; it < 4; it++) {
            int i = tid + it * 224;
            if (i < HW4) t4[i] = xp4[i];
        }
    }

    // Per-channel constants.
    float w0 = dw_w[c*9+0], w1 = dw_w[c*9+1], w2 = dw_w[c*9+2];
    float w3 = dw_w[c*9+3], w4 = dw_w[c*9+4], w5 = dw_w[c*9+5];
    float w6 = dw_w[c*9+6], w7 = dw_w[c*9+7], w8 = dw_w[c*9+8];
    const float bias = dw_b[c];
    const float inv  = g1[c] * rsqrtf(v1[c] + EPS);
    const float add  = b1[c] - m1[c] * inv;

    const int w   = tid % Wn;              // column 0..55
    const int seg = tid / Wn;              // strip 0..3
    const int h0  = seg * 14;
    const bool lOk = (w > 0), rOk = (w < Wn - 1);

    __syncthreads();

    // Rolling window registers: rows r-1, r, r+1 (cols w-1, w, w+1).
    float a0,a1,a2, b0c,b1c,b2c, c0,c1,c2;

    // load row helper (manually inlined via macro)
#define LOADROW(r, ra, rb, rc)                                   \
    if ((unsigned)(r) < (unsigned)Hn) {                          \
        int base = (r) * Wn + w;                                 \
        rb = tile[base];                                         \
        ra = lOk ? tile[base - 1] : 0.0f;                        \
        rc = rOk ? tile[base + 1] : 0.0f;                        \
    } else { ra = 0.0f; rb = 0.0f; rc = 0.0f; }

    LOADROW(h0 - 1, a0, a1, a2);
    LOADROW(h0,     b0c, b1c, b2c);

    float vals[14];
    float mx = 0.0f;
#pragma unroll
    for (int i = 0; i < 14; i++) {
        LOADROW(h0 + i + 1, c0, c1, c2);
        // three independent partial sums (short FMA chains)
        float p0 = fmaf(w0, a0, fmaf(w1, a1, w2 * a2));
        float p1 = fmaf(w3, b0c, fmaf(w4, b1c, w5 * b2c));
        float p2 = fmaf(w6, c0, fmaf(w7, c1, fmaf(w8, c2, bias)));
        float acc = p0 + p1 + p2;
        float r = fmaxf(fmaf(acc, inv, add), 0.0f);   // BN1 + ReLU
        mx = fmaxf(mx, r);
        vals[i] = r;
        a0 = b0c; a1 = b1c; a2 = b2c;
        b0c = c0; b1c = c1; b2c = c2;
    }
#undef LOADROW

    // Block max reduction over 7 warps.
    __shared__ float smax[7];
    __shared__ int   s_keep;
    const int lane = tid & 31, warp = tid >> 5;
#pragma unroll
    for (int off = 16; off; off >>= 1)
        mx = fmaxf(mx, __shfl_xor_sync(0xffffffffu, mx, off));
    if (lane == 0) smax[warp] = mx;
    __syncthreads();
    if (tid == 0) {
        float m = smax[0];
#pragma unroll
        for (int i = 1; i < 7; i++) m = fmaxf(m, smax[i]);
        int keep = (m >= DW_THR) ? 1 : 0;
        s_keep = keep;
        g_flags[plane] = keep;
    }
    __syncthreads();

    if (s_keep) {
        float* __restrict__ yp = g_y + (size_t)plane * HW + w;
#pragma unroll
        for (int i = 0; i < 14; i++)
            yp[(h0 + i) * Wn] = vals[i];
    }
}

// ---------------------------------------------------------------------------
// Kernel B: pointwise over survivors, 8 output channels per block, float4.
// One block per (b, o-group). In-kernel cut via same-thread zero rewrite.
// ---------------------------------------------------------------------------
__global__ __launch_bounds__(256)
void pw_kernel(const float* __restrict__ pw_w,   // [O,C]
               const float* __restrict__ pw_b,   // [O]
               const float* __restrict__ g2, const float* __restrict__ b2,
               const float* __restrict__ m2, const float* __restrict__ v2,
               float* __restrict__ z)
{
    const int b   = blockIdx.x >> 5;            // 32 o-groups per batch
    const int og  = (blockIdx.x & 31) * TO;     // first o of this group
    const int tid = threadIdx.x;
    const int lane = tid & 31, warp = tid >> 5;

    __shared__ int   soff4[Cn];        // survivor offsets within batch (float4 units)
    __shared__ float sw[Cn * TO];      // sw[j*TO+t] = pw_w[(og+t)*Cn + c_j]
    __shared__ int   warpcnt[8];
    __shared__ int   s_n;
    __shared__ float sbias[TO], sinv[TO], sadd[TO];
    __shared__ float swmax[8][TO];
    __shared__ int   skeep[TO];

    // Deterministic ballot-compaction of this batch's survivors.
    const int c = tid;
    const int f = g_flags[b * Cn + c];
    unsigned ball = __ballot_sync(0xffffffffu, f);
    if (lane == 0) warpcnt[warp] = __popc(ball);
    if (tid < TO) {
        int o = og + tid;
        float iv = g2[o] * rsqrtf(v2[o] + EPS);
        sbias[tid] = pw_b[o];
        sinv[tid]  = iv;
        sadd[tid]  = b2[o] - m2[o] * iv;
    }
    __syncthreads();
    int prefix = 0;
#pragma unroll
    for (int i = 0; i < 8; i++) prefix += (i < warp) ? warpcnt[i] : 0;
    if (f) {
        int pos = prefix + __popc(ball & ((1u << lane) - 1u));
        soff4[pos] = c * HW4;
#pragma unroll
        for (int t = 0; t < TO; t++)
            sw[pos * TO + t] = pw_w[(og + t) * Cn + c];
    }
    if (tid == 0) {
        int n = 0;
#pragma unroll
        for (int i = 0; i < 8; i++) n += warpcnt[i];
        s_n = n;
    }
    __syncthreads();
    const int n = s_n;

    const float4* __restrict__ yb4 = (const float4*)(g_y + (size_t)b * Cn * HW);
    float4* __restrict__ z4 = (float4*)z;
    const size_t zbase = (size_t)(b * On + og) * HW4;

    float mx[TO];
#pragma unroll
    for (int t = 0; t < TO; t++) mx[t] = 0.0f;

#pragma unroll
    for (int it = 0; it < 4; it++) {
        int idx = tid + it * 256;
        if (idx < HW4) {
            float4 acc[TO];
#pragma unroll
            for (int t = 0; t < TO; t++) {
                float bv = sbias[t];
                acc[t] = make_float4(bv, bv, bv, bv);
            }
            for (int j = 0; j < n; j++) {
                float4 yv = yb4[soff4[j] + idx];
                const float* wj = &sw[j * TO];
#pragma unroll
                for (int t = 0; t < TO; t++) {
                    float wv = wj[t];
                    acc[t].x = fmaf(wv, yv.x, acc[t].x);
                    acc[t].y = fmaf(wv, yv.y, acc[t].y);
                    acc[t].z = fmaf(wv, yv.z, acc[t].z);
                    acc[t].w = fmaf(wv, yv.w, acc[t].w);
                }
            }
#pragma unroll
            for (int t = 0; t < TO; t++) {
                float iv = sinv[t], ad = sadd[t];
                float4 r;
                r.x = fmaxf(fmaf(acc[t].x, iv, ad), 0.0f);
                r.y = fmaxf(fmaf(acc[t].y, iv, ad), 0.0f);
                r.z = fmaxf(fmaf(acc[t].z, iv, ad), 0.0f);
                r.w = fmaxf(fmaf(acc[t].w, iv, ad), 0.0f);
                mx[t] = fmaxf(mx[t], fmaxf(fmaxf(r.x, r.y), fmaxf(r.z, r.w)));
                z4[zbase + (size_t)t * HW4 + idx] = r;
            }
        }
    }

    // Per-o block max reduction.
#pragma unroll
    for (int t = 0; t < TO; t++) {
        float m = mx[t];
#pragma unroll
        for (int off = 16; off; off >>= 1)
            m = fmaxf(m, __shfl_xor_sync(0xffffffffu, m, off));
        if (lane == 0) swmax[warp][t] = m;
    }
    __syncthreads();
    if (tid < TO) {
        float m = swmax[0][tid];
#pragma unroll
        for (int i = 1; i < 8; i++) m = fmaxf(m, swmax[i][tid]);
        skeep[tid] = (m >= PW_THR) ? 1 : 0;
    }
    __syncthreads();

    // Cut planes (rare): same thread rewrites its own pixels with zeros
    // (same-address same-thread -> program-order safe).
    const float4 zero4 = make_float4(0.f, 0.f, 0.f, 0.f);
#pragma unroll
    for (int t = 0; t < TO; t++) {
        if (!skeep[t]) {
#pragma unroll
            for (int it = 0; it < 4; it++) {
                int idx = tid + it * 256;
                if (idx < HW4) z4[zbase + (size_t)t * HW4 + idx] = zero4;
            }
        }
    }
}

// ---------------------------------------------------------------------------
extern "C" void kernel_launch(void* const* d_in, const int* in_sizes, int n_in,
                              void* d_out, int out_size)
{
    const float* x    = (const float*)d_in[0];
    const float* dw_w = (const float*)d_in[1];
    const float* dw_b = (const float*)d_in[2];
    const float* pw_w = (const float*)d_in[3];
    const float* pw_b = (const float*)d_in[4];
    const float* g1   = (const float*)d_in[5];
    const float* b1   = (const float*)d_in[6];
    const float* m1   = (const float*)d_in[7];
    const float* v1   = (const float*)d_in[8];
    const float* g2   = (const float*)d_in[9];
    const float* b2   = (const float*)d_in[10];
    const float* m2   = (const float*)d_in[11];
    const float* v2   = (const float*)d_in[12];
    float* z = (float*)d_out;

    dw_kernel<<<Bn * Cn, 224>>>(x, dw_w, dw_b, g1, b1, m1, v1);
    pw_kernel<<<Bn * (On / TO), 256>>>(pw_w, pw_b, g2, b2, m2, v2, z);
}